// round 15
// baseline (speedup 1.0000x reference)
#include <cuda_runtime.h>
#include <cuda_fp16.h>
#include <mma.h>
#include <stdint.h>
#include <math.h>

using namespace nvcuda;

#define Bb 64
#define Tt 256
#define Dd 409
#define XP 416     // padded K for x/Wih
#define Hh 1024
#define G4 4096
#define TB 16384   // B*T
#define NCTA 128
#define HLD 1032   // half lead dim in recurrence smem

__device__ float  g_gx_enc[(size_t)TB*G4];      // x@Wih^T (NO bias; added in recur)
__device__ float  g_gx_dec[(size_t)TB*G4];
__device__ __half g_hs16[(size_t)TB*Hh];        // decoder h fp16 (head input)
__device__ __half g_h16[2][Bb*Hh];              // ping-pong h, fp16
__device__ __half g_x16[(size_t)TB*XP];         // x fp16, K padded
__device__ __half g_w16_enc[(size_t)G4*XP];
__device__ __half g_w16_dec[(size_t)G4*XP];
__device__ __half g_pw16[(size_t)448*Hh];       // pred_W fp16, rows padded
__device__ unsigned g_pflag[2][64];
__device__ unsigned g_cflag[2][64];

__device__ __forceinline__ float sig_f(float x){
    return 1.f / (1.f + __expf(-x));
}
__device__ __forceinline__ float tanh_f(float x){
    return 2.f / (1.f + __expf(-2.f*x)) - 1.f;
}

// ---- fused prep: x/w/pw conversions + h/flags init (ONE launch) ----
__global__ void k_prep(const float* __restrict__ x,
                       const float* __restrict__ eW, const float* __restrict__ dW,
                       const float* __restrict__ pW){
    int i = blockIdx.x*blockDim.x + threadIdx.x;
    if (i < TB*XP){
        int d = i % XP, m = i / XP;
        g_x16[i] = (d < Dd) ? __float2half_rn(x[(size_t)m*Dd + d]) : __float2half_rn(0.f);
    }
    if (i < G4*XP){
        int d = i % XP, r = i / XP;
        g_w16_enc[i] = (d < Dd) ? __float2half_rn(eW[(size_t)r*Dd + d]) : __float2half_rn(0.f);
        g_w16_dec[i] = (d < Dd) ? __float2half_rn(dW[(size_t)r*Dd + d]) : __float2half_rn(0.f);
    }
    if (i < 448*Hh){
        int r = i >> 10;
        g_pw16[i] = (r < Dd) ? __float2half_rn(pW[i]) : __float2half_rn(0.f);
    }
    if (i < Bb*Hh) g_h16[0][i] = __float2half_rn(0.f);
    if (i < 128){
        int s = i >> 6, c = i & 63;
        g_pflag[s][c] = 0u;
        g_cflag[s][c] = 0u;
    }
}

// ---- gates: BM=128 BN=128, BK=32 double-buffered, LDG.128 staging,
// direct global store. gx[m][n] = Xrow(m).Wih[n] (bias added in recur). ----
__global__ void k_gates16(const __half* __restrict__ W16,
                          float* __restrict__ gx, int shifted){
    extern __shared__ char dsm[];
    __half* As[2] = { (__half*)dsm,           (__half*)(dsm + 10240) };
    __half* Bs[2] = { (__half*)(dsm + 20480), (__half*)(dsm + 30720) };

    int tid = threadIdx.x, wid = tid >> 5;
    int m0 = blockIdx.y * 128, n0 = blockIdx.x * 128;
    int wm = (wid >> 1) * 32, wn = (wid & 1) * 64;

    wmma::fragment<wmma::accumulator,16,16,16,float> acc[2][4];
    #pragma unroll
    for (int i=0;i<2;i++)
        #pragma unroll
        for (int j=0;j<4;j++) wmma::fill_fragment(acc[i][j], 0.f);

    const uint4* X4 = (const uint4*)g_x16;   // 52 uint4 per row
    const uint4* W4 = (const uint4*)W16;
    const uint4 z4 = make_uint4(0u,0u,0u,0u);

    // load tile kt=0
    {
        uint4* Au = (uint4*)As[0];
        uint4* Bu = (uint4*)Bs[0];
        #pragma unroll
        for (int q = 0; q < 2; q++){
            int idx = tid + q*256, r = idx >> 2, q4 = idx & 3;
            int m = m0 + r;
            uint4 v = z4;
            if (!shifted)            v = X4[(size_t)m*52 + q4];
            else if ((m & 255) != 0) v = X4[(size_t)(m-1)*52 + q4];
            Au[r*5 + q4] = v;
        }
        #pragma unroll
        for (int q = 0; q < 2; q++){
            int idx = tid + q*256, r = idx >> 2, q4 = idx & 3;
            Bu[r*5 + q4] = W4[(size_t)(n0 + r)*52 + q4];
        }
    }
    __syncthreads();

    for (int kt = 0; kt < 13; kt++){
        int cur = kt & 1, nxt = cur ^ 1;
        uint4 pfa[2], pfb[2];
        if (kt < 12){
            int kb = (kt+1)*4;     // uint4 offset within row
            #pragma unroll
            for (int q = 0; q < 2; q++){
                int idx = tid + q*256, r = idx >> 2, q4 = idx & 3;
                int m = m0 + r;
                uint4 v = z4;
                if (!shifted)            v = X4[(size_t)m*52 + kb + q4];
                else if ((m & 255) != 0) v = X4[(size_t)(m-1)*52 + kb + q4];
                pfa[q] = v;
            }
            #pragma unroll
            for (int q = 0; q < 2; q++){
                int idx = tid + q*256, r = idx >> 2, q4 = idx & 3;
                pfb[q] = W4[(size_t)(n0 + r)*52 + kb + q4];
            }
        }
        #pragma unroll
        for (int sub = 0; sub < 2; sub++){
            wmma::fragment<wmma::matrix_a,16,16,16,__half,wmma::row_major> af[2];
            wmma::fragment<wmma::matrix_b,16,16,16,__half,wmma::col_major> bf[4];
            #pragma unroll
            for (int i=0;i<2;i++)
                wmma::load_matrix_sync(af[i], &As[cur][(wm + i*16)*40 + sub*16], 40);
            #pragma unroll
            for (int j=0;j<4;j++)
                wmma::load_matrix_sync(bf[j], &Bs[cur][(wn + j*16)*40 + sub*16], 40);
            #pragma unroll
            for (int i=0;i<2;i++)
                #pragma unroll
                for (int j=0;j<4;j++)
                    wmma::mma_sync(acc[i][j], af[i], bf[j], acc[i][j]);
        }
        if (kt < 12){
            uint4* Au = (uint4*)As[nxt];
            uint4* Bu = (uint4*)Bs[nxt];
            #pragma unroll
            for (int q = 0; q < 2; q++){
                int idx = tid + q*256, r = idx >> 2, q4 = idx & 3;
                Au[r*5 + q4] = pfa[q];
            }
            #pragma unroll
            for (int q = 0; q < 2; q++){
                int idx = tid + q*256, r = idx >> 2, q4 = idx & 3;
                Bu[r*5 + q4] = pfb[q];
            }
        }
        __syncthreads();
    }

    #pragma unroll
    for (int i=0;i<2;i++)
        #pragma unroll
        for (int j=0;j<4;j++)
            wmma::store_matrix_sync(&gx[(size_t)(m0 + wm + i*16)*G4 + n0 + wn + j*16],
                                    acc[i][j], G4, wmma::mem_row_major);
}

// ---- persistent recurrence (R14 structure; fast activations) ----
__global__ void __launch_bounds__(512, 1) k_recur(
    const float* __restrict__ WhhE, const float* __restrict__ WhhD,
    const float* __restrict__ encB, const float* __restrict__ decB,
    float* __restrict__ lat)
{
    extern __shared__ char smc[];
    __half* Ws  = (__half*)smc;                          // 64 x HLD
    __half* Hs  = (__half*)(smc + 64*HLD*2);             // 32 x HLD
    float*  Gs0 = (float* )(smc + 96*HLD*2);             // 32 x 68
    float*  Gs1 = Gs0 + 32*68;                           // 32 x 68

    int tid = threadIdx.x;
    int wid = tid >> 5;
    int kh = wid >> 3;
    int wm = (wid & 7) >> 2;
    int wn = wid & 3;
    int s    = blockIdx.x & 1;
    int cb   = blockIdx.x >> 1;
    int base = cb * 16;
    int boff = s * 32;

    int pw  = (tid < 256);
    int pb_ = tid >> 3;
    int pj0 = (tid & 7) * 2;

    volatile unsigned* pf = g_pflag[s];
    volatile unsigned* cf = g_cflag[s];

    for (int idx = tid; idx < 64*1024; idx += 512){
        int r = idx >> 10, k = idx & 1023;
        int grow = ((r >> 4) << 10) + base + (r & 15);
        Ws[r*HLD + k] = __float2half_rn(WhhE[(size_t)grow*1024 + k]);
    }

    float bv[8];
    if (pw){
        #pragma unroll
        for (int g = 0; g < 4; g++){
            bv[2*g]   = encB[g*1024 + base + pj0];
            bv[2*g+1] = encB[g*1024 + base + pj0 + 1];
        }
    }

    float c0 = 0.f, c1 = 0.f;
    __syncthreads();

    for (int t = 0; t < 512; t++){
        int phase = t >> 8, tt = t & 255;
        if (t == 256){
            __syncthreads();
            for (int idx = tid; idx < 64*1024; idx += 512){
                int r = idx >> 10, k = idx & 1023;
                int grow = ((r >> 4) << 10) + base + (r & 15);
                Ws[r*HLD + k] = __float2half_rn(WhhD[(size_t)grow*1024 + k]);
            }
            if (pw){
                #pragma unroll
                for (int g = 0; g < 4; g++){
                    bv[2*g]   = decB[g*1024 + base + pj0];
                    bv[2*g+1] = decB[g*1024 + base + pj0 + 1];
                }
            }
            __syncthreads();
        }
        const float* gxP = phase ? g_gx_dec : g_gx_enc;

        if (t > 0){
            if (tid < 64){ while (pf[tid] < (unsigned)t) { } }
            __syncthreads();
        }

        float gxv[8];
        if (pw){
            const float* gxr = gxP + ((size_t)(boff + pb_)*Tt + tt)*G4;
            #pragma unroll
            for (int g = 0; g < 4; g++){
                float2 v = *(const float2*)&gxr[g*1024 + base + pj0];
                gxv[2*g]   = v.x;
                gxv[2*g+1] = v.y;
            }
        }

        {
            const uint4* src = (const uint4*)g_h16[t & 1];
            uint4* dst = (uint4*)Hs;
            #pragma unroll
            for (int q = 0; q < 8; q++){
                int idx = tid + q*512;
                int row = idx >> 7, c8 = idx & 127;
                dst[row*129 + c8] = __ldcg(&src[(size_t)(boff + row)*128 + c8]);
            }
        }
        __syncthreads();
        if (tid == 0) atomicExch((unsigned*)&cf[cb], (unsigned)(t + 1));

        {
            wmma::fragment<wmma::accumulator,16,16,16,float> a0, a1;
            wmma::fill_fragment(a0, 0.f);
            wmma::fill_fragment(a1, 0.f);
            int k0 = kh * 512;
            #pragma unroll 4
            for (int k = k0; k < k0 + 512; k += 32){
                wmma::fragment<wmma::matrix_a,16,16,16,__half,wmma::row_major> af;
                wmma::fragment<wmma::matrix_b,16,16,16,__half,wmma::col_major> bf;
                wmma::load_matrix_sync(af, &Hs[(wm*16)*HLD + k], HLD);
                wmma::load_matrix_sync(bf, &Ws[(wn*16)*HLD + k], HLD);
                wmma::mma_sync(a0, af, bf, a0);
                wmma::load_matrix_sync(af, &Hs[(wm*16)*HLD + k + 16], HLD);
                wmma::load_matrix_sync(bf, &Ws[(wn*16)*HLD + k + 16], HLD);
                wmma::mma_sync(a1, af, bf, a1);
            }
            #pragma unroll
            for (int e = 0; e < a0.num_elements; e++) a0.x[e] += a1.x[e];
            float* Gdst = kh ? Gs1 : Gs0;
            wmma::store_matrix_sync(&Gdst[(wm*16)*68 + wn*16], a0, 68, wmma::mem_row_major);
        }
        __syncthreads();

        float hv[2];
        int b = boff + pb_;
        if (pw){
            #pragma unroll
            for (int p = 0; p < 2; p++){
                int j = pj0 + p;
                float iv = (Gs0[pb_*68 +      j] + Gs1[pb_*68 +      j]) + gxv[0 + p] + bv[0 + p];
                float fv = (Gs0[pb_*68 + 16 + j] + Gs1[pb_*68 + 16 + j]) + gxv[2 + p] + bv[2 + p];
                float gv = (Gs0[pb_*68 + 32 + j] + Gs1[pb_*68 + 32 + j]) + gxv[4 + p] + bv[4 + p];
                float ov = (Gs0[pb_*68 + 48 + j] + Gs1[pb_*68 + 48 + j]) + gxv[6 + p] + bv[6 + p];
                float si = sig_f(iv);
                float sf = sig_f(fv);
                float so = sig_f(ov);
                float cc = p ? c1 : c0;
                cc = sf * cc + si * tanh_f(gv);
                hv[p] = so * tanh_f(cc);
                if (p) c1 = cc; else c0 = cc;
            }
        }

        if (t > 0){
            if (tid < 64){ while (cf[tid] < (unsigned)t) { } }
            __syncthreads();
        }

        if (pw){
            __half2 hh = __floats2half2_rn(hv[0], hv[1]);
            *(__half2*)&g_h16[(t + 1) & 1][b*Hh + base + pj0] = hh;
            if (phase) *(__half2*)&g_hs16[((size_t)b*Tt + tt)*Hh + base + pj0] = hh;
            if (t == 255){
                float2 lv = make_float2(hv[0], hv[1]);
                *(float2*)&lat[b*Hh + base + pj0] = lv;
            }
        }
        __threadfence();
        __syncthreads();
        if (tid == 0) atomicExch((unsigned*)&pf[cb], (unsigned)(t + 1));
    }
}

// ---- head via WMMA (unchanged; passed) ----
__global__ void k_head16(const float* __restrict__ pb, float* __restrict__ seq){
    extern __shared__ char dsm[];
    __half* As[2] = { (__half*)dsm,              (__half*)(dsm + 10240) };
    __half* Bs[2] = { (__half*)(dsm + 20480),    (__half*)(dsm + 25600) };
    float*  Cs    = (float*)dsm;

    int tid = threadIdx.x, wid = tid >> 5;
    int m0 = blockIdx.y * 128, n0 = blockIdx.x * 64;
    int wm = (wid & 3) * 32, wn = (wid >> 2) * 32;

    wmma::fragment<wmma::accumulator,16,16,16,float> acc[2][2];
    #pragma unroll
    for (int i=0;i<2;i++)
        #pragma unroll
        for (int j=0;j<2;j++) wmma::fill_fragment(acc[i][j], 0.f);

    const uint32_t* Hu = (const uint32_t*)g_hs16;
    const uint32_t* Pu = (const uint32_t*)g_pw16;

    {
        uint32_t* Au = (uint32_t*)As[0];
        uint32_t* Bu = (uint32_t*)Bs[0];
        #pragma unroll
        for (int q = 0; q < 8; q++){
            int idx = tid + q*256, r = idx >> 4, kp = idx & 15;
            Au[r*20 + kp] = Hu[(size_t)(m0 + r)*512 + kp];
        }
        #pragma unroll
        for (int q = 0; q < 4; q++){
            int idx = tid + q*256, r = idx >> 4, kp = idx & 15;
            Bu[r*20 + kp] = Pu[(size_t)(n0 + r)*512 + kp];
        }
    }
    __syncthreads();

    for (int kt = 0; kt < 32; kt++){
        int cur = kt & 1, nxt = cur ^ 1;
        uint32_t pfa[8], pfb[4];
        if (kt < 31){
            int kb = (kt+1)*16;
            #pragma unroll
            for (int q = 0; q < 8; q++){
                int idx = tid + q*256, r = idx >> 4, kp = idx & 15;
                pfa[q] = Hu[(size_t)(m0 + r)*512 + kb + kp];
            }
            #pragma unroll
            for (int q = 0; q < 4; q++){
                int idx = tid + q*256, r = idx >> 4, kp = idx & 15;
                pfb[q] = Pu[(size_t)(n0 + r)*512 + kb + kp];
            }
        }
        #pragma unroll
        for (int sub = 0; sub < 2; sub++){
            wmma::fragment<wmma::matrix_a,16,16,16,__half,wmma::row_major> af[2];
            wmma::fragment<wmma::matrix_b,16,16,16,__half,wmma::col_major> bf[2];
            wmma::load_matrix_sync(af[0], &As[cur][(wm     )*40 + sub*16], 40);
            wmma::load_matrix_sync(af[1], &As[cur][(wm + 16)*40 + sub*16], 40);
            wmma::load_matrix_sync(bf[0], &Bs[cur][(wn     )*40 + sub*16], 40);
            wmma::load_matrix_sync(bf[1], &Bs[cur][(wn + 16)*40 + sub*16], 40);
            #pragma unroll
            for (int i=0;i<2;i++)
                #pragma unroll
                for (int j=0;j<2;j++)
                    wmma::mma_sync(acc[i][j], af[i], bf[j], acc[i][j]);
        }
        if (kt < 31){
            uint32_t* Au = (uint32_t*)As[nxt];
            uint32_t* Bu = (uint32_t*)Bs[nxt];
            #pragma unroll
            for (int q = 0; q < 8; q++){
                int idx = tid + q*256, r = idx >> 4, kp = idx & 15;
                Au[r*20 + kp] = pfa[q];
            }
            #pragma unroll
            for (int q = 0; q < 4; q++){
                int idx = tid + q*256, r = idx >> 4, kp = idx & 15;
                Bu[r*20 + kp] = pfb[q];
            }
        }
        __syncthreads();
    }

    wmma::store_matrix_sync(&Cs[(wm     )*68 + wn     ], acc[0][0], 68, wmma::mem_row_major);
    wmma::store_matrix_sync(&Cs[(wm     )*68 + wn + 16], acc[0][1], 68, wmma::mem_row_major);
    wmma::store_matrix_sync(&Cs[(wm + 16)*68 + wn     ], acc[1][0], 68, wmma::mem_row_major);
    wmma::store_matrix_sync(&Cs[(wm + 16)*68 + wn + 16], acc[1][1], 68, wmma::mem_row_major);
    __syncthreads();

    #pragma unroll
    for (int q = 0; q < 32; q++){
        int e = tid + q*256;
        int r = e >> 6, cl = e & 63;
        int n = n0 + cl;
        if (n < Dd)
            seq[(size_t)(m0 + r)*Dd + n] = Cs[r*68 + cl] + pb[n];
    }
}

static float* symaddr(const void* sym){
    void* p = 0;
    cudaGetSymbolAddress(&p, sym);
    return (float*)p;
}

extern "C" void kernel_launch(void* const* d_in, const int* in_sizes, int n_in,
                              void* d_out, int out_size) {
    const float* inputs  = (const float*)d_in[0];
    const float* enc_Wih = (const float*)d_in[1];
    const float* enc_Whh = (const float*)d_in[2];
    const float* enc_b   = (const float*)d_in[3];
    const float* dec_Wih = (const float*)d_in[4];
    const float* dec_Whh = (const float*)d_in[5];
    const float* dec_b   = (const float*)d_in[6];
    const float* pred_W  = (const float*)d_in[7];
    const float* pred_b  = (const float*)d_in[8];

    float* lat = (float*)d_out;               // [1,B,H]
    float* seq = (float*)d_out + Bb*Hh;       // [B,T,D]

    float* gxe = symaddr(g_gx_enc);
    float* gxd = symaddr(g_gx_dec);
    __half* w16e = (__half*)symaddr(g_w16_enc);
    __half* w16d = (__half*)symaddr(g_w16_dec);

    // launch #1: fused prep
    k_prep<<<(TB*XP + 255)/256, 256>>>(inputs, enc_Wih, dec_Wih, pred_W);

    // launches #2, #3: gates
    const int gsmem = 40960;
    cudaFuncSetAttribute(k_gates16, cudaFuncAttributeMaxDynamicSharedMemorySize, gsmem);
    dim3 gg(G4/128, TB/128);
    k_gates16<<<gg, 256, gsmem>>>(w16e, gxe, 0);
    k_gates16<<<gg, 256, gsmem>>>(w16d, gxd, 1);

    // launch #4: recurrence (ncu capture slot)
    const int rsmem = 96*HLD*2 + 2*32*68*4;
    cudaFuncSetAttribute(k_recur, cudaFuncAttributeMaxDynamicSharedMemorySize, rsmem);
    k_recur<<<NCTA, 512, rsmem>>>(enc_Whh, dec_Whh, enc_b, dec_b, lat);

    // launch #5: head
    const int hsmem = 35840;
    cudaFuncSetAttribute(k_head16, cudaFuncAttributeMaxDynamicSharedMemorySize, hsmem);
    dim3 hg((Dd + 63)/64, TB/128);
    k_head16<<<hg, 256, hsmem>>>(pred_b, seq);
}

// round 16
// speedup vs baseline: 1.0125x; 1.0125x over previous
#include <cuda_runtime.h>
#include <cuda_fp16.h>
#include <mma.h>
#include <stdint.h>
#include <math.h>

using namespace nvcuda;

#define Bb 64
#define Tt 256
#define Dd 409
#define XP 416     // padded K for x/Wih
#define Hh 1024
#define G4 4096
#define TB 16384   // B*T
#define NCTA 128
#define HLD 1032   // half lead dim in recurrence smem

__device__ float  g_gx_enc[(size_t)TB*G4];      // x@Wih^T (NO bias; added in recur)
__device__ float  g_gx_dec[(size_t)TB*G4];
__device__ __half g_hs16[(size_t)TB*Hh];        // decoder h fp16 (head input)
__device__ __half g_h16[2][Bb*Hh];              // ping-pong h, fp16
__device__ __half g_x16[(size_t)TB*XP];         // x fp16, K padded
__device__ __half g_w16_enc[(size_t)G4*XP];
__device__ __half g_w16_dec[(size_t)G4*XP];
__device__ __half g_pw16[(size_t)448*Hh];       // pred_W fp16, rows padded
__device__ unsigned g_pflag[2][64];
__device__ unsigned g_cflag[2][64];

__device__ __forceinline__ float sig_f(float x){
    return 1.f / (1.f + __expf(-x));
}
__device__ __forceinline__ float tanh_f(float x){
    return 2.f / (1.f + __expf(-2.f*x)) - 1.f;
}

// release/acquire flag ops (gpu scope) — single-thread release after __syncthreads
// replaces per-thread __threadfence + atomicExch (16 MEMBAR.GPU/step -> 1 release)
__device__ __forceinline__ void st_release_gpu(unsigned* p, unsigned v){
    asm volatile("st.release.gpu.global.u32 [%0], %1;" :: "l"(p), "r"(v) : "memory");
}
__device__ __forceinline__ unsigned ld_acquire_gpu(const unsigned* p){
    unsigned v;
    asm volatile("ld.acquire.gpu.global.u32 %0, [%1];" : "=r"(v) : "l"(p) : "memory");
    return v;
}

// ---- fused prep: x/w/pw conversions + h/flags init (ONE launch) ----
__global__ void k_prep(const float* __restrict__ x,
                       const float* __restrict__ eW, const float* __restrict__ dW,
                       const float* __restrict__ pW){
    int i = blockIdx.x*blockDim.x + threadIdx.x;
    if (i < TB*XP){
        int d = i % XP, m = i / XP;
        g_x16[i] = (d < Dd) ? __float2half_rn(x[(size_t)m*Dd + d]) : __float2half_rn(0.f);
    }
    if (i < G4*XP){
        int d = i % XP, r = i / XP;
        g_w16_enc[i] = (d < Dd) ? __float2half_rn(eW[(size_t)r*Dd + d]) : __float2half_rn(0.f);
        g_w16_dec[i] = (d < Dd) ? __float2half_rn(dW[(size_t)r*Dd + d]) : __float2half_rn(0.f);
    }
    if (i < 448*Hh){
        int r = i >> 10;
        g_pw16[i] = (r < Dd) ? __float2half_rn(pW[i]) : __float2half_rn(0.f);
    }
    if (i < Bb*Hh) g_h16[0][i] = __float2half_rn(0.f);
    if (i < 128){
        int s = i >> 6, c = i & 63;
        g_pflag[s][c] = 0u;
        g_cflag[s][c] = 0u;
    }
}

// ---- gates: BM=128 BN=128, BK=32 double-buffered, LDG.128 staging,
// direct global store. gx[m][n] = Xrow(m).Wih[n] (bias added in recur). ----
__global__ void k_gates16(const __half* __restrict__ W16,
                          float* __restrict__ gx, int shifted){
    extern __shared__ char dsm[];
    __half* As[2] = { (__half*)dsm,           (__half*)(dsm + 10240) };
    __half* Bs[2] = { (__half*)(dsm + 20480), (__half*)(dsm + 30720) };

    int tid = threadIdx.x, wid = tid >> 5;
    int m0 = blockIdx.y * 128, n0 = blockIdx.x * 128;
    int wm = (wid >> 1) * 32, wn = (wid & 1) * 64;

    wmma::fragment<wmma::accumulator,16,16,16,float> acc[2][4];
    #pragma unroll
    for (int i=0;i<2;i++)
        #pragma unroll
        for (int j=0;j<4;j++) wmma::fill_fragment(acc[i][j], 0.f);

    const uint4* X4 = (const uint4*)g_x16;   // 52 uint4 per row
    const uint4* W4 = (const uint4*)W16;
    const uint4 z4 = make_uint4(0u,0u,0u,0u);

    {
        uint4* Au = (uint4*)As[0];
        uint4* Bu = (uint4*)Bs[0];
        #pragma unroll
        for (int q = 0; q < 2; q++){
            int idx = tid + q*256, r = idx >> 2, q4 = idx & 3;
            int m = m0 + r;
            uint4 v = z4;
            if (!shifted)            v = X4[(size_t)m*52 + q4];
            else if ((m & 255) != 0) v = X4[(size_t)(m-1)*52 + q4];
            Au[r*5 + q4] = v;
        }
        #pragma unroll
        for (int q = 0; q < 2; q++){
            int idx = tid + q*256, r = idx >> 2, q4 = idx & 3;
            Bu[r*5 + q4] = W4[(size_t)(n0 + r)*52 + q4];
        }
    }
    __syncthreads();

    for (int kt = 0; kt < 13; kt++){
        int cur = kt & 1, nxt = cur ^ 1;
        uint4 pfa[2], pfb[2];
        if (kt < 12){
            int kb = (kt+1)*4;
            #pragma unroll
            for (int q = 0; q < 2; q++){
                int idx = tid + q*256, r = idx >> 2, q4 = idx & 3;
                int m = m0 + r;
                uint4 v = z4;
                if (!shifted)            v = X4[(size_t)m*52 + kb + q4];
                else if ((m & 255) != 0) v = X4[(size_t)(m-1)*52 + kb + q4];
                pfa[q] = v;
            }
            #pragma unroll
            for (int q = 0; q < 2; q++){
                int idx = tid + q*256, r = idx >> 2, q4 = idx & 3;
                pfb[q] = W4[(size_t)(n0 + r)*52 + kb + q4];
            }
        }
        #pragma unroll
        for (int sub = 0; sub < 2; sub++){
            wmma::fragment<wmma::matrix_a,16,16,16,__half,wmma::row_major> af[2];
            wmma::fragment<wmma::matrix_b,16,16,16,__half,wmma::col_major> bf[4];
            #pragma unroll
            for (int i=0;i<2;i++)
                wmma::load_matrix_sync(af[i], &As[cur][(wm + i*16)*40 + sub*16], 40);
            #pragma unroll
            for (int j=0;j<4;j++)
                wmma::load_matrix_sync(bf[j], &Bs[cur][(wn + j*16)*40 + sub*16], 40);
            #pragma unroll
            for (int i=0;i<2;i++)
                #pragma unroll
                for (int j=0;j<4;j++)
                    wmma::mma_sync(acc[i][j], af[i], bf[j], acc[i][j]);
        }
        if (kt < 12){
            uint4* Au = (uint4*)As[nxt];
            uint4* Bu = (uint4*)Bs[nxt];
            #pragma unroll
            for (int q = 0; q < 2; q++){
                int idx = tid + q*256, r = idx >> 2, q4 = idx & 3;
                Au[r*5 + q4] = pfa[q];
            }
            #pragma unroll
            for (int q = 0; q < 2; q++){
                int idx = tid + q*256, r = idx >> 2, q4 = idx & 3;
                Bu[r*5 + q4] = pfb[q];
            }
        }
        __syncthreads();
    }

    #pragma unroll
    for (int i=0;i<2;i++)
        #pragma unroll
        for (int j=0;j<4;j++)
            wmma::store_matrix_sync(&gx[(size_t)(m0 + wm + i*16)*G4 + n0 + wn + j*16],
                                    acc[i][j], G4, wmma::mem_row_major);
}

// ---- persistent recurrence: release/acquire handshake (single membar per CTA
// per flag), K split across warp halves, fast activations. ----
__global__ void __launch_bounds__(512, 1) k_recur(
    const float* __restrict__ WhhE, const float* __restrict__ WhhD,
    const float* __restrict__ encB, const float* __restrict__ decB,
    float* __restrict__ lat)
{
    extern __shared__ char smc[];
    __half* Ws  = (__half*)smc;                          // 64 x HLD
    __half* Hs  = (__half*)(smc + 64*HLD*2);             // 32 x HLD
    float*  Gs0 = (float* )(smc + 96*HLD*2);             // 32 x 68
    float*  Gs1 = Gs0 + 32*68;                           // 32 x 68

    int tid = threadIdx.x;
    int wid = tid >> 5;
    int kh = wid >> 3;
    int wm = (wid & 7) >> 2;
    int wn = wid & 3;
    int s    = blockIdx.x & 1;
    int cb   = blockIdx.x >> 1;
    int base = cb * 16;
    int boff = s * 32;

    int pw  = (tid < 256);
    int pb_ = tid >> 3;
    int pj0 = (tid & 7) * 2;

    unsigned* pf = g_pflag[s];
    unsigned* cf = g_cflag[s];

    for (int idx = tid; idx < 64*1024; idx += 512){
        int r = idx >> 10, k = idx & 1023;
        int grow = ((r >> 4) << 10) + base + (r & 15);
        Ws[r*HLD + k] = __float2half_rn(WhhE[(size_t)grow*1024 + k]);
    }

    float bv[8];
    if (pw){
        #pragma unroll
        for (int g = 0; g < 4; g++){
            bv[2*g]   = encB[g*1024 + base + pj0];
            bv[2*g+1] = encB[g*1024 + base + pj0 + 1];
        }
    }

    float c0 = 0.f, c1 = 0.f;
    __syncthreads();

    for (int t = 0; t < 512; t++){
        int phase = t >> 8, tt = t & 255;
        if (t == 256){
            __syncthreads();
            for (int idx = tid; idx < 64*1024; idx += 512){
                int r = idx >> 10, k = idx & 1023;
                int grow = ((r >> 4) << 10) + base + (r & 15);
                Ws[r*HLD + k] = __float2half_rn(WhhD[(size_t)grow*1024 + k]);
            }
            if (pw){
                #pragma unroll
                for (int g = 0; g < 4; g++){
                    bv[2*g]   = decB[g*1024 + base + pj0];
                    bv[2*g+1] = decB[g*1024 + base + pj0 + 1];
                }
            }
            __syncthreads();
        }
        const float* gxP = phase ? g_gx_dec : g_gx_enc;

        // forward wait: producers of my half published h for step t (acquire)
        if (t > 0){
            if (tid < 64){ while (ld_acquire_gpu(&pf[tid]) < (unsigned)t) { } }
            __syncthreads();
        }

        float gxv[8];
        if (pw){
            const float* gxr = gxP + ((size_t)(boff + pb_)*Tt + tt)*G4;
            #pragma unroll
            for (int g = 0; g < 4; g++){
                float2 v = *(const float2*)&gxr[g*1024 + base + pj0];
                gxv[2*g]   = v.x;
                gxv[2*g+1] = v.y;
            }
        }

        {
            const uint4* src = (const uint4*)g_h16[t & 1];
            uint4* dst = (uint4*)Hs;
            #pragma unroll
            for (int q = 0; q < 8; q++){
                int idx = tid + q*512;
                int row = idx >> 7, c8 = idx & 127;
                dst[row*129 + c8] = __ldcg(&src[(size_t)(boff + row)*128 + c8]);
            }
        }
        __syncthreads();
        if (tid == 0) st_release_gpu(&cf[cb], (unsigned)(t + 1));   // done reading buf

        {
            wmma::fragment<wmma::accumulator,16,16,16,float> a0, a1;
            wmma::fill_fragment(a0, 0.f);
            wmma::fill_fragment(a1, 0.f);
            int k0 = kh * 512;
            #pragma unroll 4
            for (int k = k0; k < k0 + 512; k += 32){
                wmma::fragment<wmma::matrix_a,16,16,16,__half,wmma::row_major> af;
                wmma::fragment<wmma::matrix_b,16,16,16,__half,wmma::col_major> bf;
                wmma::load_matrix_sync(af, &Hs[(wm*16)*HLD + k], HLD);
                wmma::load_matrix_sync(bf, &Ws[(wn*16)*HLD + k], HLD);
                wmma::mma_sync(a0, af, bf, a0);
                wmma::load_matrix_sync(af, &Hs[(wm*16)*HLD + k + 16], HLD);
                wmma::load_matrix_sync(bf, &Ws[(wn*16)*HLD + k + 16], HLD);
                wmma::mma_sync(a1, af, bf, a1);
            }
            #pragma unroll
            for (int e = 0; e < a0.num_elements; e++) a0.x[e] += a1.x[e];
            float* Gdst = kh ? Gs1 : Gs0;
            wmma::store_matrix_sync(&Gdst[(wm*16)*68 + wn*16], a0, 68, wmma::mem_row_major);
        }
        __syncthreads();

        float hv[2];
        int b = boff + pb_;
        if (pw){
            #pragma unroll
            for (int p = 0; p < 2; p++){
                int j = pj0 + p;
                float iv = (Gs0[pb_*68 +      j] + Gs1[pb_*68 +      j]) + gxv[0 + p] + bv[0 + p];
                float fv = (Gs0[pb_*68 + 16 + j] + Gs1[pb_*68 + 16 + j]) + gxv[2 + p] + bv[2 + p];
                float gv = (Gs0[pb_*68 + 32 + j] + Gs1[pb_*68 + 32 + j]) + gxv[4 + p] + bv[4 + p];
                float ov = (Gs0[pb_*68 + 48 + j] + Gs1[pb_*68 + 48 + j]) + gxv[6 + p] + bv[6 + p];
                float si = sig_f(iv);
                float sf = sig_f(fv);
                float so = sig_f(ov);
                float cc = p ? c1 : c0;
                cc = sf * cc + si * tanh_f(gv);
                hv[p] = so * tanh_f(cc);
                if (p) c1 = cc; else c0 = cc;
            }
        }

        // backward wait: consumers done reading the buffer I'm about to write
        if (t > 0){
            if (tid < 64){ while (ld_acquire_gpu(&cf[tid]) < (unsigned)t) { } }
            __syncthreads();
        }

        if (pw){
            __half2 hh = __floats2half2_rn(hv[0], hv[1]);
            *(__half2*)&g_h16[(t + 1) & 1][b*Hh + base + pj0] = hh;
            if (phase) *(__half2*)&g_hs16[((size_t)b*Tt + tt)*Hh + base + pj0] = hh;
            if (t == 255){
                float2 lv = make_float2(hv[0], hv[1]);
                *(float2*)&lat[b*Hh + base + pj0] = lv;
            }
        }
        __syncthreads();                                  // block-wide hb for release below
        if (tid == 0) st_release_gpu(&pf[cb], (unsigned)(t + 1));
    }
}

// ---- head via WMMA (unchanged; passed) ----
__global__ void k_head16(const float* __restrict__ pb, float* __restrict__ seq){
    extern __shared__ char dsm[];
    __half* As[2] = { (__half*)dsm,              (__half*)(dsm + 10240) };
    __half* Bs[2] = { (__half*)(dsm + 20480),    (__half*)(dsm + 25600) };
    float*  Cs    = (float*)dsm;

    int tid = threadIdx.x, wid = tid >> 5;
    int m0 = blockIdx.y * 128, n0 = blockIdx.x * 64;
    int wm = (wid & 3) * 32, wn = (wid >> 2) * 32;

    wmma::fragment<wmma::accumulator,16,16,16,float> acc[2][2];
    #pragma unroll
    for (int i=0;i<2;i++)
        #pragma unroll
        for (int j=0;j<2;j++) wmma::fill_fragment(acc[i][j], 0.f);

    const uint32_t* Hu = (const uint32_t*)g_hs16;
    const uint32_t* Pu = (const uint32_t*)g_pw16;

    {
        uint32_t* Au = (uint32_t*)As[0];
        uint32_t* Bu = (uint32_t*)Bs[0];
        #pragma unroll
        for (int q = 0; q < 8; q++){
            int idx = tid + q*256, r = idx >> 4, kp = idx & 15;
            Au[r*20 + kp] = Hu[(size_t)(m0 + r)*512 + kp];
        }
        #pragma unroll
        for (int q = 0; q < 4; q++){
            int idx = tid + q*256, r = idx >> 4, kp = idx & 15;
            Bu[r*20 + kp] = Pu[(size_t)(n0 + r)*512 + kp];
        }
    }
    __syncthreads();

    for (int kt = 0; kt < 32; kt++){
        int cur = kt & 1, nxt = cur ^ 1;
        uint32_t pfa[8], pfb[4];
        if (kt < 31){
            int kb = (kt+1)*16;
            #pragma unroll
            for (int q = 0; q < 8; q++){
                int idx = tid + q*256, r = idx >> 4, kp = idx & 15;
                pfa[q] = Hu[(size_t)(m0 + r)*512 + kb + kp];
            }
            #pragma unroll
            for (int q = 0; q < 4; q++){
                int idx = tid + q*256, r = idx >> 4, kp = idx & 15;
                pfb[q] = Pu[(size_t)(n0 + r)*512 + kb + kp];
            }
        }
        #pragma unroll
        for (int sub = 0; sub < 2; sub++){
            wmma::fragment<wmma::matrix_a,16,16,16,__half,wmma::row_major> af[2];
            wmma::fragment<wmma::matrix_b,16,16,16,__half,wmma::col_major> bf[2];
            wmma::load_matrix_sync(af[0], &As[cur][(wm     )*40 + sub*16], 40);
            wmma::load_matrix_sync(af[1], &As[cur][(wm + 16)*40 + sub*16], 40);
            wmma::load_matrix_sync(bf[0], &Bs[cur][(wn     )*40 + sub*16], 40);
            wmma::load_matrix_sync(bf[1], &Bs[cur][(wn + 16)*40 + sub*16], 40);
            #pragma unroll
            for (int i=0;i<2;i++)
                #pragma unroll
                for (int j=0;j<2;j++)
                    wmma::mma_sync(acc[i][j], af[i], bf[j], acc[i][j]);
        }
        if (kt < 31){
            uint32_t* Au = (uint32_t*)As[nxt];
            uint32_t* Bu = (uint32_t*)Bs[nxt];
            #pragma unroll
            for (int q = 0; q < 8; q++){
                int idx = tid + q*256, r = idx >> 4, kp = idx & 15;
                Au[r*20 + kp] = pfa[q];
            }
            #pragma unroll
            for (int q = 0; q < 4; q++){
                int idx = tid + q*256, r = idx >> 4, kp = idx & 15;
                Bu[r*20 + kp] = pfb[q];
            }
        }
        __syncthreads();
    }

    wmma::store_matrix_sync(&Cs[(wm     )*68 + wn     ], acc[0][0], 68, wmma::mem_row_major);
    wmma::store_matrix_sync(&Cs[(wm     )*68 + wn + 16], acc[0][1], 68, wmma::mem_row_major);
    wmma::store_matrix_sync(&Cs[(wm + 16)*68 + wn     ], acc[1][0], 68, wmma::mem_row_major);
    wmma::store_matrix_sync(&Cs[(wm + 16)*68 + wn + 16], acc[1][1], 68, wmma::mem_row_major);
    __syncthreads();

    #pragma unroll
    for (int q = 0; q < 32; q++){
        int e = tid + q*256;
        int r = e >> 6, cl = e & 63;
        int n = n0 + cl;
        if (n < Dd)
            seq[(size_t)(m0 + r)*Dd + n] = Cs[r*68 + cl] + pb[n];
    }
}

static float* symaddr(const void* sym){
    void* p = 0;
    cudaGetSymbolAddress(&p, sym);
    return (float*)p;
}

extern "C" void kernel_launch(void* const* d_in, const int* in_sizes, int n_in,
                              void* d_out, int out_size) {
    const float* inputs  = (const float*)d_in[0];
    const float* enc_Wih = (const float*)d_in[1];
    const float* enc_Whh = (const float*)d_in[2];
    const float* enc_b   = (const float*)d_in[3];
    const float* dec_Wih = (const float*)d_in[4];
    const float* dec_Whh = (const float*)d_in[5];
    const float* dec_b   = (const float*)d_in[6];
    const float* pred_W  = (const float*)d_in[7];
    const float* pred_b  = (const float*)d_in[8];

    float* lat = (float*)d_out;               // [1,B,H]
    float* seq = (float*)d_out + Bb*Hh;       // [B,T,D]

    float* gxe = symaddr(g_gx_enc);
    float* gxd = symaddr(g_gx_dec);
    __half* w16e = (__half*)symaddr(g_w16_enc);
    __half* w16d = (__half*)symaddr(g_w16_dec);

    // launch #1: fused prep
    k_prep<<<(TB*XP + 255)/256, 256>>>(inputs, enc_Wih, dec_Wih, pred_W);

    // launches #2, #3: gates
    const int gsmem = 40960;
    cudaFuncSetAttribute(k_gates16, cudaFuncAttributeMaxDynamicSharedMemorySize, gsmem);
    dim3 gg(G4/128, TB/128);
    k_gates16<<<gg, 256, gsmem>>>(w16e, gxe, 0);
    k_gates16<<<gg, 256, gsmem>>>(w16d, gxd, 1);

    // launch #4: recurrence (ncu capture slot)
    const int rsmem = 96*HLD*2 + 2*32*68*4;
    cudaFuncSetAttribute(k_recur, cudaFuncAttributeMaxDynamicSharedMemorySize, rsmem);
    k_recur<<<NCTA, 512, rsmem>>>(enc_Whh, dec_Whh, enc_b, dec_b, lat);

    // launch #5: head
    const int hsmem = 35840;
    cudaFuncSetAttribute(k_head16, cudaFuncAttributeMaxDynamicSharedMemorySize, hsmem);
    dim3 hg((Dd + 63)/64, TB/128);
    k_head16<<<hg, 256, hsmem>>>(pred_b, seq);
}

// round 17
// speedup vs baseline: 1.0810x; 1.0677x over previous
#include <cuda_runtime.h>
#include <cuda_fp16.h>
#include <mma.h>
#include <stdint.h>
#include <math.h>

using namespace nvcuda;

#define Bb 64
#define Tt 256
#define Dd 409
#define XP 416     // padded K for x/Wih
#define Hh 1024
#define G4 4096
#define TB 16384   // B*T
#define NCTA 128
#define HLD 1032   // half lead dim in recurrence smem

__device__ float  g_gx_enc[(size_t)TB*G4];      // x@Wih^T (NO bias; added in recur)
__device__ float  g_gx_dec[(size_t)TB*G4];
__device__ __half g_hs16[(size_t)TB*Hh];        // decoder h fp16 (head input)
__device__ __half g_h16[2][Bb*Hh];              // ping-pong h, fp16
__device__ __half g_x16[(size_t)TB*XP];         // x fp16, K padded
__device__ __half g_w16_enc[(size_t)G4*XP];
__device__ __half g_w16_dec[(size_t)G4*XP];
__device__ __half g_pw16[(size_t)448*Hh];       // pred_W fp16, rows padded
__device__ unsigned g_pflag[2][64];             // producer step counters (per half)

__device__ __forceinline__ float sig_f(float x){
    return 1.f / (1.f + __expf(-x));
}
__device__ __forceinline__ float tanh_f(float x){
    return 2.f / (1.f + __expf(-2.f*x)) - 1.f;
}

__device__ __forceinline__ void st_release_gpu(unsigned* p, unsigned v){
    asm volatile("st.release.gpu.global.u32 [%0], %1;" :: "l"(p), "r"(v) : "memory");
}
__device__ __forceinline__ unsigned ld_acquire_gpu(const unsigned* p){
    unsigned v;
    asm volatile("ld.acquire.gpu.global.u32 %0, [%1];" : "=r"(v) : "l"(p) : "memory");
    return v;
}

// ---- fused prep: x/w/pw conversions + h/flags init (ONE launch) ----
__global__ void k_prep(const float* __restrict__ x,
                       const float* __restrict__ eW, const float* __restrict__ dW,
                       const float* __restrict__ pW){
    int i = blockIdx.x*blockDim.x + threadIdx.x;
    if (i < TB*XP){
        int d = i % XP, m = i / XP;
        g_x16[i] = (d < Dd) ? __float2half_rn(x[(size_t)m*Dd + d]) : __float2half_rn(0.f);
    }
    if (i < G4*XP){
        int d = i % XP, r = i / XP;
        g_w16_enc[i] = (d < Dd) ? __float2half_rn(eW[(size_t)r*Dd + d]) : __float2half_rn(0.f);
        g_w16_dec[i] = (d < Dd) ? __float2half_rn(dW[(size_t)r*Dd + d]) : __float2half_rn(0.f);
    }
    if (i < 448*Hh){
        int r = i >> 10;
        g_pw16[i] = (r < Dd) ? __float2half_rn(pW[i]) : __float2half_rn(0.f);
    }
    if (i < Bb*Hh) g_h16[0][i] = __float2half_rn(0.f);
    if (i < 128) g_pflag[i >> 6][i & 63] = 0u;
}

// ---- gates (unchanged from R16; passed): BM=128 BN=128, BK=32, LDG.128 ----
__global__ void k_gates16(const __half* __restrict__ W16,
                          float* __restrict__ gx, int shifted){
    extern __shared__ char dsm[];
    __half* As[2] = { (__half*)dsm,           (__half*)(dsm + 10240) };
    __half* Bs[2] = { (__half*)(dsm + 20480), (__half*)(dsm + 30720) };

    int tid = threadIdx.x, wid = tid >> 5;
    int m0 = blockIdx.y * 128, n0 = blockIdx.x * 128;
    int wm = (wid >> 1) * 32, wn = (wid & 1) * 64;

    wmma::fragment<wmma::accumulator,16,16,16,float> acc[2][4];
    #pragma unroll
    for (int i=0;i<2;i++)
        #pragma unroll
        for (int j=0;j<4;j++) wmma::fill_fragment(acc[i][j], 0.f);

    const uint4* X4 = (const uint4*)g_x16;   // 52 uint4 per row
    const uint4* W4 = (const uint4*)W16;
    const uint4 z4 = make_uint4(0u,0u,0u,0u);

    {
        uint4* Au = (uint4*)As[0];
        uint4* Bu = (uint4*)Bs[0];
        #pragma unroll
        for (int q = 0; q < 2; q++){
            int idx = tid + q*256, r = idx >> 2, q4 = idx & 3;
            int m = m0 + r;
            uint4 v = z4;
            if (!shifted)            v = X4[(size_t)m*52 + q4];
            else if ((m & 255) != 0) v = X4[(size_t)(m-1)*52 + q4];
            Au[r*5 + q4] = v;
        }
        #pragma unroll
        for (int q = 0; q < 2; q++){
            int idx = tid + q*256, r = idx >> 2, q4 = idx & 3;
            Bu[r*5 + q4] = W4[(size_t)(n0 + r)*52 + q4];
        }
    }
    __syncthreads();

    for (int kt = 0; kt < 13; kt++){
        int cur = kt & 1, nxt = cur ^ 1;
        uint4 pfa[2], pfb[2];
        if (kt < 12){
            int kb = (kt+1)*4;
            #pragma unroll
            for (int q = 0; q < 2; q++){
                int idx = tid + q*256, r = idx >> 2, q4 = idx & 3;
                int m = m0 + r;
                uint4 v = z4;
                if (!shifted)            v = X4[(size_t)m*52 + kb + q4];
                else if ((m & 255) != 0) v = X4[(size_t)(m-1)*52 + kb + q4];
                pfa[q] = v;
            }
            #pragma unroll
            for (int q = 0; q < 2; q++){
                int idx = tid + q*256, r = idx >> 2, q4 = idx & 3;
                pfb[q] = W4[(size_t)(n0 + r)*52 + kb + q4];
            }
        }
        #pragma unroll
        for (int sub = 0; sub < 2; sub++){
            wmma::fragment<wmma::matrix_a,16,16,16,__half,wmma::row_major> af[2];
            wmma::fragment<wmma::matrix_b,16,16,16,__half,wmma::col_major> bf[4];
            #pragma unroll
            for (int i=0;i<2;i++)
                wmma::load_matrix_sync(af[i], &As[cur][(wm + i*16)*40 + sub*16], 40);
            #pragma unroll
            for (int j=0;j<4;j++)
                wmma::load_matrix_sync(bf[j], &Bs[cur][(wn + j*16)*40 + sub*16], 40);
            #pragma unroll
            for (int i=0;i<2;i++)
                #pragma unroll
                for (int j=0;j<4;j++)
                    wmma::mma_sync(acc[i][j], af[i], bf[j], acc[i][j]);
        }
        if (kt < 12){
            uint4* Au = (uint4*)As[nxt];
            uint4* Bu = (uint4*)Bs[nxt];
            #pragma unroll
            for (int q = 0; q < 2; q++){
                int idx = tid + q*256, r = idx >> 2, q4 = idx & 3;
                Au[r*5 + q4] = pfa[q];
            }
            #pragma unroll
            for (int q = 0; q < 2; q++){
                int idx = tid + q*256, r = idx >> 2, q4 = idx & 3;
                Bu[r*5 + q4] = pfb[q];
            }
        }
        __syncthreads();
    }

    #pragma unroll
    for (int i=0;i<2;i++)
        #pragma unroll
        for (int j=0;j<4;j++)
            wmma::store_matrix_sync(&gx[(size_t)(m0 + wm + i*16)*G4 + n0 + wn + j*16],
                                    acc[i][j], G4, wmma::mem_row_major);
}

// ---- persistent recurrence v6: forward-only handshake (cf proven redundant),
// chunked gather pipelined under MMA, gx prefetch hoisted before the poll. ----
__global__ void __launch_bounds__(512, 1) k_recur(
    const float* __restrict__ WhhE, const float* __restrict__ WhhD,
    const float* __restrict__ encB, const float* __restrict__ decB,
    float* __restrict__ lat)
{
    extern __shared__ char smc[];
    __half* Ws  = (__half*)smc;                          // 64 x HLD
    __half* Hs  = (__half*)(smc + 64*HLD*2);             // 32 x HLD
    float*  Gs0 = (float* )(smc + 96*HLD*2);             // 32 x 68
    float*  Gs1 = Gs0 + 32*68;                           // 32 x 68

    int tid = threadIdx.x;
    int wid = tid >> 5;
    int kh = wid >> 3;           // K-interleave parity
    int wm = (wid & 7) >> 2;
    int wn = wid & 3;
    int s    = blockIdx.x & 1;
    int cb   = blockIdx.x >> 1;
    int base = cb * 16;
    int boff = s * 32;

    int pw  = (tid < 256);
    int pb_ = tid >> 3;
    int pj0 = (tid & 7) * 2;

    unsigned* pf = g_pflag[s];

    for (int idx = tid; idx < 64*1024; idx += 512){
        int r = idx >> 10, k = idx & 1023;
        int grow = ((r >> 4) << 10) + base + (r & 15);
        Ws[r*HLD + k] = __float2half_rn(WhhE[(size_t)grow*1024 + k]);
    }

    float bv[8];
    if (pw){
        #pragma unroll
        for (int g = 0; g < 4; g++){
            bv[2*g]   = encB[g*1024 + base + pj0];
            bv[2*g+1] = encB[g*1024 + base + pj0 + 1];
        }
    }

    float c0 = 0.f, c1 = 0.f;
    __syncthreads();

    for (int t = 0; t < 512; t++){
        int phase = t >> 8, tt = t & 255;
        if (t == 256){
            __syncthreads();
            for (int idx = tid; idx < 64*1024; idx += 512){
                int r = idx >> 10, k = idx & 1023;
                int grow = ((r >> 4) << 10) + base + (r & 15);
                Ws[r*HLD + k] = __float2half_rn(WhhD[(size_t)grow*1024 + k]);
            }
            if (pw){
                #pragma unroll
                for (int g = 0; g < 4; g++){
                    bv[2*g]   = decB[g*1024 + base + pj0];
                    bv[2*g+1] = decB[g*1024 + base + pj0 + 1];
                }
            }
            __syncthreads();
        }
        const float* gxP = phase ? g_gx_dec : g_gx_enc;

        // gx prefetch BEFORE the poll (no peer dependency; latency fully hidden)
        float gxv[8];
        if (pw){
            const float* gxr = gxP + ((size_t)(boff + pb_)*Tt + tt)*G4;
            #pragma unroll
            for (int g = 0; g < 4; g++){
                float2 v = *(const float2*)&gxr[g*1024 + base + pj0];
                gxv[2*g]   = v.x;
                gxv[2*g+1] = v.y;
            }
        }

        // forward wait: peers of my half published h for step t (acquire).
        // (backward/cf wait removed: pf>=t already implies all peers finished
        //  their step t-1 gather of buffer (t+1)&1, so overwriting it is safe.)
        if (t > 0){
            if (tid < 64){ while (ld_acquire_gpu(&pf[tid]) < (unsigned)t) { } }
            __syncthreads();
        }

        const uint4* src = (const uint4*)g_h16[t & 1];
        uint4* dst = (uint4*)Hs;

        // gather chunk 0 (uint4 cols 0..31 = halves 0..255)
        #pragma unroll
        for (int q = 0; q < 2; q++){
            int idx = tid + q*512, row = idx >> 5, cc = idx & 31;
            dst[row*129 + cc] = __ldcg(&src[(size_t)(boff + row)*128 + cc]);
        }
        __syncthreads();

        // pipelined chunks: MMA chunk c while staging chunk c+1
        wmma::fragment<wmma::accumulator,16,16,16,float> a0, a1;
        wmma::fill_fragment(a0, 0.f);
        wmma::fill_fragment(a1, 0.f);

        #pragma unroll
        for (int c = 0; c < 4; c++){
            uint4 pf4[2];
            if (c < 3){
                int cb4 = (c+1)*32;
                #pragma unroll
                for (int q = 0; q < 2; q++){
                    int idx = tid + q*512, row = idx >> 5, cc = idx & 31;
                    pf4[q] = __ldcg(&src[(size_t)(boff + row)*128 + cb4 + cc]);
                }
            }
            // warp's K share this chunk: [c*256 + kh*128, +128)
            int k0 = c*256 + kh*128;
            #pragma unroll
            for (int i = 0; i < 4; i++){
                int k = k0 + i*32;
                wmma::fragment<wmma::matrix_a,16,16,16,__half,wmma::row_major> af;
                wmma::fragment<wmma::matrix_b,16,16,16,__half,wmma::col_major> bf;
                wmma::load_matrix_sync(af, &Hs[(wm*16)*HLD + k], HLD);
                wmma::load_matrix_sync(bf, &Ws[(wn*16)*HLD + k], HLD);
                wmma::mma_sync(a0, af, bf, a0);
                wmma::load_matrix_sync(af, &Hs[(wm*16)*HLD + k + 16], HLD);
                wmma::load_matrix_sync(bf, &Ws[(wn*16)*HLD + k + 16], HLD);
                wmma::mma_sync(a1, af, bf, a1);
            }
            if (c < 3){
                int cb4 = (c+1)*32;
                #pragma unroll
                for (int q = 0; q < 2; q++){
                    int idx = tid + q*512, row = idx >> 5, cc = idx & 31;
                    dst[row*129 + cb4 + cc] = pf4[q];
                }
                __syncthreads();
            }
        }

        #pragma unroll
        for (int e = 0; e < a0.num_elements; e++) a0.x[e] += a1.x[e];
        float* Gdst = kh ? Gs1 : Gs0;
        wmma::store_matrix_sync(&Gdst[(wm*16)*68 + wn*16], a0, 68, wmma::mem_row_major);
        __syncthreads();

        // pointwise (threads <256)
        float hv[2];
        int b = boff + pb_;
        if (pw){
            #pragma unroll
            for (int p = 0; p < 2; p++){
                int j = pj0 + p;
                float iv = (Gs0[pb_*68 +      j] + Gs1[pb_*68 +      j]) + gxv[0 + p] + bv[0 + p];
                float fv = (Gs0[pb_*68 + 16 + j] + Gs1[pb_*68 + 16 + j]) + gxv[2 + p] + bv[2 + p];
                float gv = (Gs0[pb_*68 + 32 + j] + Gs1[pb_*68 + 32 + j]) + gxv[4 + p] + bv[4 + p];
                float ov = (Gs0[pb_*68 + 48 + j] + Gs1[pb_*68 + 48 + j]) + gxv[6 + p] + bv[6 + p];
                float si = sig_f(iv);
                float sf = sig_f(fv);
                float so = sig_f(ov);
                float cc = p ? c1 : c0;
                cc = sf * cc + si * tanh_f(gv);
                hv[p] = so * tanh_f(cc);
                if (p) c1 = cc; else c0 = cc;

                __half2 hh2;  // stores below
            }
            __half2 hh = __floats2half2_rn(hv[0], hv[1]);
            *(__half2*)&g_h16[(t + 1) & 1][b*Hh + base + pj0] = hh;
            if (phase) *(__half2*)&g_hs16[((size_t)b*Tt + tt)*Hh + base + pj0] = hh;
            if (t == 255){
                float2 lv = make_float2(hv[0], hv[1]);
                *(float2*)&lat[b*Hh + base + pj0] = lv;
            }
        }
        __syncthreads();                                  // all h stores done
        if (tid == 0) st_release_gpu(&pf[cb], (unsigned)(t + 1));
    }
}

// ---- head via WMMA (unchanged; passed) ----
__global__ void k_head16(const float* __restrict__ pb, float* __restrict__ seq){
    extern __shared__ char dsm[];
    __half* As[2] = { (__half*)dsm,              (__half*)(dsm + 10240) };
    __half* Bs[2] = { (__half*)(dsm + 20480),    (__half*)(dsm + 25600) };
    float*  Cs    = (float*)dsm;

    int tid = threadIdx.x, wid = tid >> 5;
    int m0 = blockIdx.y * 128, n0 = blockIdx.x * 64;
    int wm = (wid & 3) * 32, wn = (wid >> 2) * 32;

    wmma::fragment<wmma::accumulator,16,16,16,float> acc[2][2];
    #pragma unroll
    for (int i=0;i<2;i++)
        #pragma unroll
        for (int j=0;j<2;j++) wmma::fill_fragment(acc[i][j], 0.f);

    const uint32_t* Hu = (const uint32_t*)g_hs16;
    const uint32_t* Pu = (const uint32_t*)g_pw16;

    {
        uint32_t* Au = (uint32_t*)As[0];
        uint32_t* Bu = (uint32_t*)Bs[0];
        #pragma unroll
        for (int q = 0; q < 8; q++){
            int idx = tid + q*256, r = idx >> 4, kp = idx & 15;
            Au[r*20 + kp] = Hu[(size_t)(m0 + r)*512 + kp];
        }
        #pragma unroll
        for (int q = 0; q < 4; q++){
            int idx = tid + q*256, r = idx >> 4, kp = idx & 15;
            Bu[r*20 + kp] = Pu[(size_t)(n0 + r)*512 + kp];
        }
    }
    __syncthreads();

    for (int kt = 0; kt < 32; kt++){
        int cur = kt & 1, nxt = cur ^ 1;
        uint32_t pfa[8], pfb[4];
        if (kt < 31){
            int kb = (kt+1)*16;
            #pragma unroll
            for (int q = 0; q < 8; q++){
                int idx = tid + q*256, r = idx >> 4, kp = idx & 15;
                pfa[q] = Hu[(size_t)(m0 + r)*512 + kb + kp];
            }
            #pragma unroll
            for (int q = 0; q < 4; q++){
                int idx = tid + q*256, r = idx >> 4, kp = idx & 15;
                pfb[q] = Pu[(size_t)(n0 + r)*512 + kb + kp];
            }
        }
        #pragma unroll
        for (int sub = 0; sub < 2; sub++){
            wmma::fragment<wmma::matrix_a,16,16,16,__half,wmma::row_major> af[2];
            wmma::fragment<wmma::matrix_b,16,16,16,__half,wmma::col_major> bf[2];
            wmma::load_matrix_sync(af[0], &As[cur][(wm     )*40 + sub*16], 40);
            wmma::load_matrix_sync(af[1], &As[cur][(wm + 16)*40 + sub*16], 40);
            wmma::load_matrix_sync(bf[0], &Bs[cur][(wn     )*40 + sub*16], 40);
            wmma::load_matrix_sync(bf[1], &Bs[cur][(wn + 16)*40 + sub*16], 40);
            #pragma unroll
            for (int i=0;i<2;i++)
                #pragma unroll
                for (int j=0;j<2;j++)
                    wmma::mma_sync(acc[i][j], af[i], bf[j], acc[i][j]);
        }
        if (kt < 31){
            uint32_t* Au = (uint32_t*)As[nxt];
            uint32_t* Bu = (uint32_t*)Bs[nxt];
            #pragma unroll
            for (int q = 0; q < 8; q++){
                int idx = tid + q*256, r = idx >> 4, kp = idx & 15;
                Au[r*20 + kp] = pfa[q];
            }
            #pragma unroll
            for (int q = 0; q < 4; q++){
                int idx = tid + q*256, r = idx >> 4, kp = idx & 15;
                Bu[r*20 + kp] = pfb[q];
            }
        }
        __syncthreads();
    }

    wmma::store_matrix_sync(&Cs[(wm     )*68 + wn     ], acc[0][0], 68, wmma::mem_row_major);
    wmma::store_matrix_sync(&Cs[(wm     )*68 + wn + 16], acc[0][1], 68, wmma::mem_row_major);
    wmma::store_matrix_sync(&Cs[(wm + 16)*68 + wn     ], acc[1][0], 68, wmma::mem_row_major);
    wmma::store_matrix_sync(&Cs[(wm + 16)*68 + wn + 16], acc[1][1], 68, wmma::mem_row_major);
    __syncthreads();

    #pragma unroll
    for (int q = 0; q < 32; q++){
        int e = tid + q*256;
        int r = e >> 6, cl = e & 63;
        int n = n0 + cl;
        if (n < Dd)
            seq[(size_t)(m0 + r)*Dd + n] = Cs[r*68 + cl] + pb[n];
    }
}

static float* symaddr(const void* sym){
    void* p = 0;
    cudaGetSymbolAddress(&p, sym);
    return (float*)p;
}

extern "C" void kernel_launch(void* const* d_in, const int* in_sizes, int n_in,
                              void* d_out, int out_size) {
    const float* inputs  = (const float*)d_in[0];
    const float* enc_Wih = (const float*)d_in[1];
    const float* enc_Whh = (const float*)d_in[2];
    const float* enc_b   = (const float*)d_in[3];
    const float* dec_Wih = (const float*)d_in[4];
    const float* dec_Whh = (const float*)d_in[5];
    const float* dec_b   = (const float*)d_in[6];
    const float* pred_W  = (const float*)d_in[7];
    const float* pred_b  = (const float*)d_in[8];

    float* lat = (float*)d_out;               // [1,B,H]
    float* seq = (float*)d_out + Bb*Hh;       // [B,T,D]

    float* gxe = symaddr(g_gx_enc);
    float* gxd = symaddr(g_gx_dec);
    __half* w16e = (__half*)symaddr(g_w16_enc);
    __half* w16d = (__half*)symaddr(g_w16_dec);

    // launch #1: fused prep
    k_prep<<<(TB*XP + 255)/256, 256>>>(inputs, enc_Wih, dec_Wih, pred_W);

    // launches #2, #3: gates
    const int gsmem = 40960;
    cudaFuncSetAttribute(k_gates16, cudaFuncAttributeMaxDynamicSharedMemorySize, gsmem);
    dim3 gg(G4/128, TB/128);
    k_gates16<<<gg, 256, gsmem>>>(w16e, gxe, 0);
    k_gates16<<<gg, 256, gsmem>>>(w16d, gxd, 1);

    // launch #4: recurrence (ncu capture slot)
    const int rsmem = 96*HLD*2 + 2*32*68*4;
    cudaFuncSetAttribute(k_recur, cudaFuncAttributeMaxDynamicSharedMemorySize, rsmem);
    k_recur<<<NCTA, 512, rsmem>>>(enc_Whh, dec_Whh, enc_b, dec_b, lat);

    // launch #5: head
    const int hsmem = 35840;
    cudaFuncSetAttribute(k_head16, cudaFuncAttributeMaxDynamicSharedMemorySize, hsmem);
    dim3 hg((Dd + 63)/64, TB/128);
    k_head16<<<hg, 256, hsmem>>>(pred_b, seq);
}